// round 1
// baseline (speedup 1.0000x reference)
#include <cuda_runtime.h>
#include <math.h>

#define TPB 256
#define PA 72      // padded leading dim of transposed A tile [64 d][64 rows]
#define PW 132     // padded leading dim of transposed W tile [64 d][128 cols]

// smem layout (floats):
//  sAT  : 64*72   = 4608
//  sWT  : 64*132  = 8448
//  sK   : 64*256  = 16384   (reused as sHF [16][1024] in FF phase)
//  sV   : 64*256  = 16384
//  sQ   : 16*256  = 4096    (reused as Oh, then as sY)
//  sAO  : 16*256  = 4096
//  sGH  : 16*64   = 1024
//  sGate: 16
#define SMEM_FLOATS (4608 + 8448 + 16384 + 16384 + 4096 + 4096 + 1024 + 16)
#define SMEM_BYTES  (SMEM_FLOATS * 4)

#define OUT_GATE_BASE 33554432UL   // B*M*D = 32768*4*256

static __device__ __forceinline__ void ldAT(const float* __restrict__ A, int rows, int stride,
                                            float* sAT, int tid) {
    // A[r][q*4 .. q*4+3] -> sAT[d][r], tile is 64 d wide
    const int total = rows * 16;
    for (int idx = tid; idx < total; idx += TPB) {
        const int r = idx >> 4, q = idx & 15;
        const float4 v = *reinterpret_cast<const float4*>(A + (size_t)r * stride + (q << 2));
        const int d = q << 2;
        sAT[(d + 0) * PA + r] = v.x;
        sAT[(d + 1) * PA + r] = v.y;
        sAT[(d + 2) * PA + r] = v.z;
        sAT[(d + 3) * PA + r] = v.w;
    }
}

static __device__ __forceinline__ void ldWT(const float* __restrict__ W, int ncols, int ld,
                                            float* sWT, int tid) {
    // W[c][q*4 .. q*4+3] -> sWT[d][c], tile is 64 d wide
    const int total = ncols * 16;
    for (int idx = tid; idx < total; idx += TPB) {
        const int c = idx >> 4, q = idx & 15;
        const float4 v = *reinterpret_cast<const float4*>(W + (size_t)c * ld + (q << 2));
        const int d = q << 2;
        sWT[(d + 0) * PW + c] = v.x;
        sWT[(d + 1) * PW + c] = v.y;
        sWT[(d + 2) * PW + c] = v.z;
        sWT[(d + 3) * PW + c] = v.w;
    }
}

static __device__ __forceinline__ void mma64(const float* sAT, const float* sWT,
                                             float* acc, int tr, int tc) {
#pragma unroll 8
    for (int d = 0; d < 64; ++d) {
        const float4 a4  = *reinterpret_cast<const float4*>(sAT + d * PA + (tr << 2));
        const float4 w04 = *reinterpret_cast<const float4*>(sWT + d * PW + (tc << 3));
        const float4 w14 = *reinterpret_cast<const float4*>(sWT + d * PW + (tc << 3) + 4);
        const float a[4] = {a4.x, a4.y, a4.z, a4.w};
        const float w[8] = {w04.x, w04.y, w04.z, w04.w, w14.x, w14.y, w14.z, w14.w};
#pragma unroll
        for (int i = 0; i < 4; ++i)
#pragma unroll
            for (int j = 0; j < 8; ++j)
                acc[i * 8 + j] = fmaf(a[i], w[j], acc[i * 8 + j]);
    }
}

static __device__ __forceinline__ void mma16(const float* sAT, const float* sWT,
                                             float* acc, int row, int tc) {
#pragma unroll 8
    for (int d = 0; d < 64; ++d) {
        const float a = sAT[d * PA + row];
        const float4 w04 = *reinterpret_cast<const float4*>(sWT + d * PW + (tc << 3));
        const float4 w14 = *reinterpret_cast<const float4*>(sWT + d * PW + (tc << 3) + 4);
        const float w[8] = {w04.x, w04.y, w04.z, w04.w, w14.x, w14.y, w14.z, w14.w};
#pragma unroll
        for (int j = 0; j < 8; ++j)
            acc[j] = fmaf(a, w[j], acc[j]);
    }
}

static __device__ __forceinline__ void mma16x4(const float* sAT, const float* sWT,
                                               float* acc, int row, int tc) {
#pragma unroll 8
    for (int d = 0; d < 64; ++d) {
        const float a = sAT[d * PA + row];
        const float4 w4 = *reinterpret_cast<const float4*>(sWT + d * PW + (tc << 2));
        acc[0] = fmaf(a, w4.x, acc[0]);
        acc[1] = fmaf(a, w4.y, acc[1]);
        acc[2] = fmaf(a, w4.z, acc[2]);
        acc[3] = fmaf(a, w4.w, acc[3]);
    }
}

__global__ __launch_bounds__(TPB, 1)
void gcma_kernel(const float* __restrict__ x,
                 const float* __restrict__ Wq, const float* __restrict__ bq,
                 const float* __restrict__ Wk, const float* __restrict__ bk,
                 const float* __restrict__ Wv, const float* __restrict__ bv,
                 const float* __restrict__ Wo, const float* __restrict__ bo,
                 const float* __restrict__ g1w, const float* __restrict__ g1b,
                 const float* __restrict__ g2w, const float* __restrict__ g2b,
                 const float* __restrict__ lng, const float* __restrict__ lnb,
                 const float* __restrict__ f1w, const float* __restrict__ f1b,
                 const float* __restrict__ f2w, const float* __restrict__ f2b,
                 float* __restrict__ out)
{
    extern __shared__ float sm[];
    float* sAT   = sm;                // 4608
    float* sWT   = sm + 4608;         // 8448
    float* sK    = sm + 13056;        // 16384
    float* sV    = sm + 29440;        // 16384
    float* sQ    = sm + 45824;        // 4096  (Oh, then Y)
    float* sAO   = sm + 49920;        // 4096
    float* sGH   = sm + 54016;        // 1024
    float* sGate = sm + 55040;        // 16
    float* sHF   = sK;                // [16][1024] reuse
    float* sY    = sQ;                // [16][256]  reuse

    const int tid = threadIdx.x;
    const int m   = blockIdx.y;
    const int b0  = blockIdx.x * 16;
    const long g0 = (long)b0 * 4;     // first global x row of this block

    const int tr = tid >> 4;          // 0..15
    const int tc = tid & 15;          // 0..15

    const float* Xblk = x + (size_t)g0 * 256;   // 64 contiguous rows

    // ======== K and V projections: [64 x 256] = Xblk @ W[m]^T + b ========
    for (int kv = 0; kv < 2; ++kv) {
        const float* W    = (kv ? Wv : Wk) + (size_t)m * 65536;
        const float* bias = (kv ? bv : bk) + m * 256;
        float* sOut = kv ? sV : sK;
        for (int kh = 0; kh < 2; ++kh) {
            float acc[32];
#pragma unroll
            for (int i = 0; i < 32; ++i) acc[i] = 0.f;
            for (int dt = 0; dt < 4; ++dt) {
                __syncthreads();
                ldAT(Xblk + dt * 64, 64, 256, sAT, tid);
                ldWT(W + (size_t)(kh * 128) * 256 + dt * 64, 128, 256, sWT, tid);
                __syncthreads();
                mma64(sAT, sWT, acc, tr, tc);
            }
#pragma unroll
            for (int i = 0; i < 4; ++i) {
                const int r = tr * 4 + i;
#pragma unroll
                for (int j = 0; j < 8; ++j) {
                    const int c = kh * 128 + tc * 8 + j;
                    sOut[r * 256 + c] = acc[i * 8 + j] + bias[c];
                }
            }
        }
    }

    // ======== Q projection: [16 x 256], scaled by 1/sqrt(HD) ========
    {
        const float* W    = Wq + (size_t)m * 65536;
        const float* bias = bq + m * 256;
        const float* A    = x + (size_t)(g0 + m) * 256;   // row stride 1024
        for (int kh = 0; kh < 2; ++kh) {
            float acc[8];
#pragma unroll
            for (int j = 0; j < 8; ++j) acc[j] = 0.f;
            for (int dt = 0; dt < 4; ++dt) {
                __syncthreads();
                ldAT(A + dt * 64, 16, 1024, sAT, tid);
                ldWT(W + (size_t)(kh * 128) * 256 + dt * 64, 128, 256, sWT, tid);
                __syncthreads();
                mma16(sAT, sWT, acc, tr, tc);
            }
#pragma unroll
            for (int j = 0; j < 8; ++j) {
                const int c = kh * 128 + tc * 8 + j;
                sQ[tr * 256 + c] = (acc[j] + bias[c]) * 0.17677669529663687f;
            }
        }
    }
    __syncthreads();

    // ======== attention: seq-len 4 softmax per (b,h); Oh overwrites sQ ========
    if (tid < 128) {
        const int bl = tid >> 3, h = tid & 7;
        const float* qp = sQ + bl * 256 + h * 32;
        float q[32];
#pragma unroll
        for (int i = 0; i < 32; ++i) q[i] = qp[i];
        float s[4];
#pragma unroll
        for (int n = 0; n < 4; ++n) {
            const float* kp = sK + (bl * 4 + n) * 256 + h * 32;
            float dot = 0.f;
#pragma unroll
            for (int i = 0; i < 32; ++i) dot = fmaf(q[i], kp[i], dot);
            s[n] = dot;
        }
        const float mx = fmaxf(fmaxf(s[0], s[1]), fmaxf(s[2], s[3]));
        float e[4], se = 0.f;
#pragma unroll
        for (int n = 0; n < 4; ++n) { e[n] = expf(s[n] - mx); se += e[n]; }
        const float inv = 1.f / se;
        float o[32];
#pragma unroll
        for (int i = 0; i < 32; ++i) o[i] = 0.f;
#pragma unroll
        for (int n = 0; n < 4; ++n) {
            const float p = e[n] * inv;
            const float* vp = sV + (bl * 4 + n) * 256 + h * 32;
#pragma unroll
            for (int i = 0; i < 32; ++i) o[i] = fmaf(p, vp[i], o[i]);
        }
        float* op = sQ + bl * 256 + h * 32;
#pragma unroll
        for (int i = 0; i < 32; ++i) op[i] = o[i];
    }
    __syncthreads();

    // ======== attn_out = Oh @ Wo[m]^T + bo : [16 x 256] ========
    {
        const float* W    = Wo + (size_t)m * 65536;
        const float* bias = bo + m * 256;
        for (int kh = 0; kh < 2; ++kh) {
            float acc[8];
#pragma unroll
            for (int j = 0; j < 8; ++j) acc[j] = 0.f;
            for (int dt = 0; dt < 4; ++dt) {
                __syncthreads();
                ldAT(sQ + dt * 64, 16, 256, sAT, tid);
                ldWT(W + (size_t)(kh * 128) * 256 + dt * 64, 128, 256, sWT, tid);
                __syncthreads();
                mma16(sAT, sWT, acc, tr, tc);
            }
#pragma unroll
            for (int j = 0; j < 8; ++j) {
                const int c = kh * 128 + tc * 8 + j;
                sAO[tr * 256 + c] = acc[j] + bias[c];
            }
        }
    }

    // ======== gate layer 1: tanh([x;attn] @ g1w[m]^T + g1b) : [16 x 64] ========
    {
        const float* W    = g1w + (size_t)m * 32768;   // [64][512]
        const float* bias = g1b + m * 64;
        float acc[4] = {0.f, 0.f, 0.f, 0.f};
        for (int dt = 0; dt < 8; ++dt) {
            __syncthreads();
            if (dt < 4) ldAT(x + (size_t)(g0 + m) * 256 + dt * 64, 16, 1024, sAT, tid);
            else        ldAT(sAO + (dt - 4) * 64, 16, 256, sAT, tid);
            ldWT(W + dt * 64, 64, 512, sWT, tid);
            __syncthreads();
            mma16x4(sAT, sWT, acc, tr, tc);
        }
#pragma unroll
        for (int j = 0; j < 4; ++j) {
            const int c = tc * 4 + j;
            sGH[tr * 64 + c] = tanhf(acc[j] + bias[c]);
        }
    }
    __syncthreads();

    // ======== gate layer 2 + sigmoid; write gate output ========
    if (tid < 16) {
        const float* g2 = g2w + m * 64;
        float dot = g2b[m];
#pragma unroll 8
        for (int j = 0; j < 64; ++j) dot = fmaf(sGH[tid * 64 + j], g2[j], dot);
        const float gate = 1.f / (1.f + expf(-dot));
        sGate[tid] = gate;
        out[OUT_GATE_BASE + (size_t)(b0 + tid) * 4 + m] = gate;
    }
    __syncthreads();

    // ======== residual + LayerNorm -> sY ========
    {
        const int w = tid >> 5, lane = tid & 31;
        for (int bl = w; bl < 16; bl += 8) {
            const float* xr = x + (size_t)(g0 + bl * 4 + m) * 256;
            const float gate = sGate[bl];
            float r[8];
            float sum = 0.f;
#pragma unroll
            for (int k = 0; k < 8; ++k) {
                const int d = k * 32 + lane;
                r[k] = xr[d] + gate * sAO[bl * 256 + d];
                sum += r[k];
            }
#pragma unroll
            for (int o = 16; o; o >>= 1) sum += __shfl_xor_sync(0xffffffffu, sum, o);
            const float mu = sum * (1.f / 256.f);
            float var = 0.f;
#pragma unroll
            for (int k = 0; k < 8; ++k) { const float t = r[k] - mu; var = fmaf(t, t, var); }
#pragma unroll
            for (int o = 16; o; o >>= 1) var += __shfl_xor_sync(0xffffffffu, var, o);
            const float rs = rsqrtf(var * (1.f / 256.f) + 1e-5f);
#pragma unroll
            for (int k = 0; k < 8; ++k) {
                const int d = k * 32 + lane;
                sY[bl * 256 + d] = (r[k] - mu) * rs * lng[m * 256 + d] + lnb[m * 256 + d];
            }
        }
    }
    __syncthreads();

    // ======== FF1: gelu(y @ f1w[m]^T + f1b) : [16 x 1024] -> sHF ========
    {
        const float* W    = f1w + (size_t)m * 262144;  // [1024][256]
        const float* bias = f1b + m * 1024;
        for (int kh = 0; kh < 8; ++kh) {
            float acc[8];
#pragma unroll
            for (int j = 0; j < 8; ++j) acc[j] = 0.f;
            for (int dt = 0; dt < 4; ++dt) {
                __syncthreads();
                ldAT(sY + dt * 64, 16, 256, sAT, tid);
                ldWT(W + (size_t)(kh * 128) * 256 + dt * 64, 128, 256, sWT, tid);
                __syncthreads();
                mma16(sAT, sWT, acc, tr, tc);
            }
#pragma unroll
            for (int j = 0; j < 8; ++j) {
                const int c = kh * 128 + tc * 8 + j;
                const float v = acc[j] + bias[c];
                sHF[tr * 1024 + c] = 0.5f * v * (1.f + erff(v * 0.7071067811865476f));
            }
        }
    }

    // ======== FF2: out = y + hf @ f2w[m]^T + f2b : [16 x 256] ========
    {
        const float* W    = f2w + (size_t)m * 262144;  // [256][1024]
        const float* bias = f2b + m * 256;
        for (int kh = 0; kh < 2; ++kh) {
            float acc[8];
#pragma unroll
            for (int j = 0; j < 8; ++j) acc[j] = 0.f;
            for (int dt = 0; dt < 16; ++dt) {
                __syncthreads();
                ldAT(sHF + dt * 64, 16, 1024, sAT, tid);
                ldWT(W + (size_t)(kh * 128) * 1024 + dt * 64, 128, 1024, sWT, tid);
                __syncthreads();
                mma16(sAT, sWT, acc, tr, tc);
            }
#pragma unroll
            for (int j = 0; j < 8; ++j) {
                const int c = kh * 128 + tc * 8 + j;
                const float v = sY[tr * 256 + c] + acc[j] + bias[c];
                out[((size_t)(b0 + tr) * 4 + m) * 256 + c] = v;
            }
        }
    }
}

extern "C" void kernel_launch(void* const* d_in, const int* in_sizes, int n_in,
                              void* d_out, int out_size) {
    const float* x   = (const float*)d_in[0];
    const float* Wq  = (const float*)d_in[1];
    const float* bq  = (const float*)d_in[2];
    const float* Wk  = (const float*)d_in[3];
    const float* bk  = (const float*)d_in[4];
    const float* Wv  = (const float*)d_in[5];
    const float* bv  = (const float*)d_in[6];
    const float* Wo  = (const float*)d_in[7];
    const float* bo  = (const float*)d_in[8];
    const float* g1w = (const float*)d_in[9];
    const float* g1b = (const float*)d_in[10];
    const float* g2w = (const float*)d_in[11];
    const float* g2b = (const float*)d_in[12];
    const float* lng = (const float*)d_in[13];
    const float* lnb = (const float*)d_in[14];
    const float* f1w = (const float*)d_in[15];
    const float* f1b = (const float*)d_in[16];
    const float* f2w = (const float*)d_in[17];
    const float* f2b = (const float*)d_in[18];
    float* out = (float*)d_out;

    cudaFuncSetAttribute(gcma_kernel, cudaFuncAttributeMaxDynamicSharedMemorySize, SMEM_BYTES);

    dim3 grid(32768 / 16, 4, 1);
    gcma_kernel<<<grid, TPB, SMEM_BYTES>>>(x, Wq, bq, Wk, bk, Wv, bv, Wo, bo,
                                           g1w, g1b, g2w, g2b, lng, lnb,
                                           f1w, f1b, f2w, f2b, out);
}

// round 2
// speedup vs baseline: 3.0717x; 3.0717x over previous
#include <cuda_runtime.h>
#include <math.h>

typedef unsigned long long u64;

#define TPB 256
#define PA 72      // pitch of sAT [32 d][rows]
#define PW 260     // pitch of sWT [32 d][cols<=256]

#define OUT_GATE_BASE 33554432UL   // B*M*D

// y scratch: [B,M,D] fp32 = 128MB
__device__ float g_y[32768u * 4u * 256u];

// ---------- packed fp32 helpers (Blackwell f32x2) ----------
static __device__ __forceinline__ u64 ffma2(u64 a, u64 b, u64 c) {
    u64 d;
    asm("fma.rn.f32x2 %0, %1, %2, %3;" : "=l"(d) : "l"(a), "l"(b), "l"(c));
    return d;
}
static __device__ __forceinline__ u64 dup2(float a) {
    u64 d;
    asm("mov.b64 %0, {%1, %1};" : "=l"(d) : "f"(a));
    return d;
}
static __device__ __forceinline__ float2 unpk(u64 p) {
    float2 r;
    asm("mov.b64 {%0, %1}, %2;" : "=f"(r.x), "=f"(r.y) : "l"(p));
    return r;
}

// ---------- tile staging ----------
// A[r][c0 + 0..31] -> sAT[d][r]   (A may be global or shared)
template<int R>
static __device__ __forceinline__ void ldA32(const float* __restrict__ A, int lda, int c0,
                                             float* sAT, int tid) {
    for (int idx = tid; idx < R * 8; idx += TPB) {
        const int r = idx >> 3, q = idx & 7;
        const float4 v = *reinterpret_cast<const float4*>(A + (size_t)r * lda + c0 + (q << 2));
        const int d = q << 2;
        sAT[(d + 0) * PA + r] = v.x;
        sAT[(d + 1) * PA + r] = v.y;
        sAT[(d + 2) * PA + r] = v.z;
        sAT[(d + 3) * PA + r] = v.w;
    }
}

// W[c][c0 + 0..31] -> sWT[d][c], c < ncols
static __device__ __forceinline__ void ldW32(const float* __restrict__ W, int ncols, int ldw,
                                             int c0, float* sWT, int tid) {
    for (int idx = tid; idx < ncols * 8; idx += TPB) {
        const int c = idx >> 3, q = idx & 7;
        const float4 v = *reinterpret_cast<const float4*>(W + (size_t)c * ldw + c0 + (q << 2));
        const int d = q << 2;
        sWT[(d + 0) * PW + c] = v.x;
        sWT[(d + 1) * PW + c] = v.y;
        sWT[(d + 2) * PW + c] = v.z;
        sWT[(d + 3) * PW + c] = v.w;
    }
}

// 8x8 tile mma over one 32-d tile: rowg=tid>>5 (8 rows), colg=tid&31 (8 cols)
static __device__ __forceinline__ void mma8x8(const float* sAT, const float* sWT,
                                              u64 acc[8][4], int rowg, int colg) {
#pragma unroll 8
    for (int d = 0; d < 32; ++d) {
        const float* ap = sAT + d * PA + (rowg << 3);
        const float4 a0 = *reinterpret_cast<const float4*>(ap);
        const float4 a1 = *reinterpret_cast<const float4*>(ap + 4);
        const ulonglong2 w0 = *reinterpret_cast<const ulonglong2*>(sWT + d * PW + (colg << 3));
        const ulonglong2 w1 = *reinterpret_cast<const ulonglong2*>(sWT + d * PW + (colg << 3) + 4);
        const float a[8] = {a0.x, a0.y, a0.z, a0.w, a1.x, a1.y, a1.z, a1.w};
#pragma unroll
        for (int i = 0; i < 8; ++i) {
            const u64 ad = dup2(a[i]);
            acc[i][0] = ffma2(ad, w0.x, acc[i][0]);
            acc[i][1] = ffma2(ad, w0.y, acc[i][1]);
            acc[i][2] = ffma2(ad, w1.x, acc[i][2]);
            acc[i][3] = ffma2(ad, w1.y, acc[i][3]);
        }
    }
}

// 4x4 tile mma (16-row GEMMs): rowg4=tid>>6 (4 rows), cg=tid&63 (4 cols)
static __device__ __forceinline__ void mma4x4(const float* sAT, const float* sWT,
                                              u64 acc[4][2], int rowg4, int cg) {
#pragma unroll 8
    for (int d = 0; d < 32; ++d) {
        const float4 a4 = *reinterpret_cast<const float4*>(sAT + d * PA + (rowg4 << 2));
        const ulonglong2 w = *reinterpret_cast<const ulonglong2*>(sWT + d * PW + (cg << 2));
        const float a[4] = {a4.x, a4.y, a4.z, a4.w};
#pragma unroll
        for (int i = 0; i < 4; ++i) {
            const u64 ad = dup2(a[i]);
            acc[i][0] = ffma2(ad, w.x, acc[i][0]);
            acc[i][1] = ffma2(ad, w.y, acc[i][1]);
        }
    }
}

// =====================================================================
// Kernel 1: KV proj + attention + Wo + gate + LayerNorm -> g_y, gate->out
// grid (2048, 4), 16 batch elements per block
// =====================================================================
#define SM1_AT   0
#define SM1_WT   2304
#define SM1_K    10624
#define SM1_V    27008
#define SM1_Q    43392
#define SM1_AO   47488
#define SM1_GH   51584
#define SM1_GATE 52608
#define SM1_FLOATS (52624)
#define SM1_BYTES  (SM1_FLOATS * 4)

__global__ __launch_bounds__(TPB, 1)
void gcma_part1(const float* __restrict__ x,
                const float* __restrict__ Wq, const float* __restrict__ bq,
                const float* __restrict__ Wk, const float* __restrict__ bk,
                const float* __restrict__ Wv, const float* __restrict__ bv,
                const float* __restrict__ Wo, const float* __restrict__ bo,
                const float* __restrict__ g1w, const float* __restrict__ g1b,
                const float* __restrict__ g2w, const float* __restrict__ g2b,
                const float* __restrict__ lng, const float* __restrict__ lnb,
                float* __restrict__ out)
{
    extern __shared__ float sm[];
    float* sAT   = sm + SM1_AT;
    float* sWT   = sm + SM1_WT;
    float* sK    = sm + SM1_K;
    float* sV    = sm + SM1_V;
    float* sQ    = sm + SM1_Q;
    float* sAO   = sm + SM1_AO;
    float* sGH   = sm + SM1_GH;
    float* sGate = sm + SM1_GATE;

    const int tid = threadIdx.x;
    const int m   = blockIdx.y;
    const int b0  = blockIdx.x * 16;
    const long g0 = (long)b0 * 4;

    const int rowg  = tid >> 5;   // 0..7
    const int colg  = tid & 31;   // 0..31
    const int rowg4 = tid >> 6;   // 0..3
    const int cg    = tid & 63;   // 0..63

    const float* Xblk = x + (size_t)g0 * 256;

    // ---- K and V: [64 x 256] ----
    for (int kv = 0; kv < 2; ++kv) {
        const float* W    = (kv ? Wv : Wk) + (size_t)m * 65536;
        const float* bias = (kv ? bv : bk) + m * 256;
        float* sOut = kv ? sV : sK;
        u64 acc[8][4];
#pragma unroll
        for (int i = 0; i < 8; ++i)
#pragma unroll
            for (int j = 0; j < 4; ++j) acc[i][j] = 0ULL;
        for (int dt = 0; dt < 8; ++dt) {
            __syncthreads();
            ldA32<64>(Xblk, 256, dt * 32, sAT, tid);
            ldW32(W, 256, 256, dt * 32, sWT, tid);
            __syncthreads();
            mma8x8(sAT, sWT, acc, rowg, colg);
        }
        float bl[8];
#pragma unroll
        for (int j = 0; j < 8; ++j) bl[j] = bias[colg * 8 + j];
#pragma unroll
        for (int i = 0; i < 8; ++i) {
            const int r = rowg * 8 + i;
            const float2 p0 = unpk(acc[i][0]), p1 = unpk(acc[i][1]);
            const float2 p2 = unpk(acc[i][2]), p3 = unpk(acc[i][3]);
            float4 o0 = make_float4(p0.x + bl[0], p0.y + bl[1], p1.x + bl[2], p1.y + bl[3]);
            float4 o1 = make_float4(p2.x + bl[4], p2.y + bl[5], p3.x + bl[6], p3.y + bl[7]);
            *reinterpret_cast<float4*>(sOut + r * 256 + colg * 8)     = o0;
            *reinterpret_cast<float4*>(sOut + r * 256 + colg * 8 + 4) = o1;
        }
    }

    // ---- Q: [16 x 256], scaled ----
    {
        const float* W    = Wq + (size_t)m * 65536;
        const float* bias = bq + m * 256;
        const float* A    = x + (size_t)(g0 + m) * 256;   // stride 1024
        u64 acc[4][2];
#pragma unroll
        for (int i = 0; i < 4; ++i) { acc[i][0] = 0ULL; acc[i][1] = 0ULL; }
        for (int dt = 0; dt < 8; ++dt) {
            __syncthreads();
            ldA32<16>(A, 1024, dt * 32, sAT, tid);
            ldW32(W, 256, 256, dt * 32, sWT, tid);
            __syncthreads();
            mma4x4(sAT, sWT, acc, rowg4, cg);
        }
        const float b0c = bias[cg * 4], b1c = bias[cg * 4 + 1];
        const float b2c = bias[cg * 4 + 2], b3c = bias[cg * 4 + 3];
#pragma unroll
        for (int i = 0; i < 4; ++i) {
            const int r = rowg4 * 4 + i;
            const float2 p0 = unpk(acc[i][0]), p1 = unpk(acc[i][1]);
            float4 o = make_float4((p0.x + b0c) * 0.17677669529663687f,
                                   (p0.y + b1c) * 0.17677669529663687f,
                                   (p1.x + b2c) * 0.17677669529663687f,
                                   (p1.y + b3c) * 0.17677669529663687f);
            *reinterpret_cast<float4*>(sQ + r * 256 + cg * 4) = o;
        }
    }
    __syncthreads();

    // ---- attention (seq 4), Oh overwrites sQ ----
    if (tid < 128) {
        const int bl = tid >> 3, h = tid & 7;
        const float* qp = sQ + bl * 256 + h * 32;
        float q[32];
#pragma unroll
        for (int i = 0; i < 32; ++i) q[i] = qp[i];
        float s[4];
#pragma unroll
        for (int n = 0; n < 4; ++n) {
            const float* kp = sK + (bl * 4 + n) * 256 + h * 32;
            float dot = 0.f;
#pragma unroll
            for (int i = 0; i < 32; ++i) dot = fmaf(q[i], kp[i], dot);
            s[n] = dot;
        }
        const float mx = fmaxf(fmaxf(s[0], s[1]), fmaxf(s[2], s[3]));
        float e[4], se = 0.f;
#pragma unroll
        for (int n = 0; n < 4; ++n) { e[n] = expf(s[n] - mx); se += e[n]; }
        const float inv = 1.f / se;
        float o[32];
#pragma unroll
        for (int i = 0; i < 32; ++i) o[i] = 0.f;
#pragma unroll
        for (int n = 0; n < 4; ++n) {
            const float p = e[n] * inv;
            const float* vp = sV + (bl * 4 + n) * 256 + h * 32;
#pragma unroll
            for (int i = 0; i < 32; ++i) o[i] = fmaf(p, vp[i], o[i]);
        }
        float* op = sQ + bl * 256 + h * 32;
#pragma unroll
        for (int i = 0; i < 32; ++i) op[i] = o[i];
    }
    __syncthreads();

    // ---- Wo: attn_out [16 x 256] -> sAO ----
    {
        const float* W    = Wo + (size_t)m * 65536;
        const float* bias = bo + m * 256;
        u64 acc[4][2];
#pragma unroll
        for (int i = 0; i < 4; ++i) { acc[i][0] = 0ULL; acc[i][1] = 0ULL; }
        for (int dt = 0; dt < 8; ++dt) {
            __syncthreads();
            ldA32<16>(sQ, 256, dt * 32, sAT, tid);
            ldW32(W, 256, 256, dt * 32, sWT, tid);
            __syncthreads();
            mma4x4(sAT, sWT, acc, rowg4, cg);
        }
        const float b0c = bias[cg * 4], b1c = bias[cg * 4 + 1];
        const float b2c = bias[cg * 4 + 2], b3c = bias[cg * 4 + 3];
#pragma unroll
        for (int i = 0; i < 4; ++i) {
            const int r = rowg4 * 4 + i;
            const float2 p0 = unpk(acc[i][0]), p1 = unpk(acc[i][1]);
            float4 o = make_float4(p0.x + b0c, p0.y + b1c, p1.x + b2c, p1.y + b3c);
            *reinterpret_cast<float4*>(sAO + r * 256 + cg * 4) = o;
        }
    }

    // ---- gate layer 1: [16 x 64] ----
    {
        const float* W = g1w + (size_t)m * 32768;   // [64][512]
        float gacc[4] = {0.f, 0.f, 0.f, 0.f};
        for (int dt = 0; dt < 16; ++dt) {
            __syncthreads();
            if (dt < 8) ldA32<16>(x + (size_t)(g0 + m) * 256, 1024, dt * 32, sAT, tid);
            else        ldA32<16>(sAO, 256, (dt - 8) * 32, sAT, tid);
            ldW32(W, 64, 512, dt * 32, sWT, tid);
            __syncthreads();
#pragma unroll 8
            for (int d = 0; d < 32; ++d) {
                const float4 a4 = *reinterpret_cast<const float4*>(sAT + d * PA + (rowg4 << 2));
                const float w = sWT[d * PW + cg];
                gacc[0] = fmaf(a4.x, w, gacc[0]);
                gacc[1] = fmaf(a4.y, w, gacc[1]);
                gacc[2] = fmaf(a4.z, w, gacc[2]);
                gacc[3] = fmaf(a4.w, w, gacc[3]);
            }
        }
        const float gb = g1b[m * 64 + cg];
#pragma unroll
        for (int i = 0; i < 4; ++i)
            sGH[(rowg4 * 4 + i) * 64 + cg] = tanhf(gacc[i] + gb);
    }
    __syncthreads();

    // ---- gate layer 2 + sigmoid ----
    if (tid < 16) {
        const float* g2 = g2w + m * 64;
        float dot = g2b[m];
#pragma unroll 8
        for (int j = 0; j < 64; ++j) dot = fmaf(sGH[tid * 64 + j], g2[j], dot);
        const float gate = 1.f / (1.f + expf(-dot));
        sGate[tid] = gate;
        out[OUT_GATE_BASE + (size_t)(b0 + tid) * 4 + m] = gate;
    }
    __syncthreads();

    // ---- residual + LayerNorm -> g_y ----
    {
        const int w = tid >> 5, lane = tid & 31;
        for (int bl = w; bl < 16; bl += 8) {
            const float* xr = x + (size_t)(g0 + bl * 4 + m) * 256;
            const float gate = sGate[bl];
            float r[8];
            float sum = 0.f;
#pragma unroll
            for (int k = 0; k < 8; ++k) {
                const int d = k * 32 + lane;
                r[k] = xr[d] + gate * sAO[bl * 256 + d];
                sum += r[k];
            }
#pragma unroll
            for (int o = 16; o; o >>= 1) sum += __shfl_xor_sync(0xffffffffu, sum, o);
            const float mu = sum * (1.f / 256.f);
            float var = 0.f;
#pragma unroll
            for (int k = 0; k < 8; ++k) { const float t = r[k] - mu; var = fmaf(t, t, var); }
#pragma unroll
            for (int o = 16; o; o >>= 1) var += __shfl_xor_sync(0xffffffffu, var, o);
            const float rs = rsqrtf(var * (1.f / 256.f) + 1e-5f);
            float* yr = g_y + (size_t)(g0 + bl * 4 + m) * 256;
#pragma unroll
            for (int k = 0; k < 8; ++k) {
                const int d = k * 32 + lane;
                yr[d] = (r[k] - mu) * rs * lng[m * 256 + d] + lnb[m * 256 + d];
            }
        }
    }
}

// =====================================================================
// Kernel 2: FF over y: out = y + f2( gelu(f1(y)) )
// grid (512, 4), 64 batch rows per block, hf chunked by 256
// =====================================================================
#define SM2_Y   0
#define SM2_HF  16640
#define SM2_AT  33280
#define SM2_WT  35584
#define SM2_FLOATS 43904
#define SM2_BYTES  (SM2_FLOATS * 4)
#define PY 260

__global__ __launch_bounds__(TPB, 1)
void gcma_part2(const float* __restrict__ f1w, const float* __restrict__ f1b,
                const float* __restrict__ f2w, const float* __restrict__ f2b,
                float* __restrict__ out)
{
    extern __shared__ float sm[];
    float* sY  = sm + SM2_Y;    // [64][260]
    float* sHF = sm + SM2_HF;   // [64][260]
    float* sAT = sm + SM2_AT;
    float* sWT = sm + SM2_WT;

    const int tid = threadIdx.x;
    const int m   = blockIdx.y;
    const int b0  = blockIdx.x * 64;

    const int rowg = tid >> 5;   // 0..7 (8 rows each)
    const int colg = tid & 31;   // 0..31 (8 cols each)

    // load y tile [64 rows][256]
    for (int idx = tid; idx < 4096; idx += TPB) {
        const int r = idx >> 6, q = idx & 63;
        const float4 v = *reinterpret_cast<const float4*>(
            g_y + ((size_t)(b0 + r) * 4 + m) * 256 + q * 4);
        *reinterpret_cast<float4*>(sY + r * PY + q * 4) = v;
    }

    u64 facc[8][4];
#pragma unroll
    for (int i = 0; i < 8; ++i)
#pragma unroll
        for (int j = 0; j < 4; ++j) facc[i][j] = 0ULL;

    for (int ch = 0; ch < 4; ++ch) {
        // ---- FF1 chunk: hf[:, ch*256 .. +255] ----
        u64 hacc[8][4];
#pragma unroll
        for (int i = 0; i < 8; ++i)
#pragma unroll
            for (int j = 0; j < 4; ++j) hacc[i][j] = 0ULL;
        const float* W1 = f1w + (size_t)m * 262144 + (size_t)ch * 65536; // rows=outcols, ld 256
        for (int dt = 0; dt < 8; ++dt) {
            __syncthreads();
            ldA32<64>(sY, PY, dt * 32, sAT, tid);
            ldW32(W1, 256, 256, dt * 32, sWT, tid);
            __syncthreads();
            mma8x8(sAT, sWT, hacc, rowg, colg);
        }
        // bias + exact GELU, store row-major into sHF
        {
            const float* b1 = f1b + m * 1024 + ch * 256 + colg * 8;
            float bl[8];
#pragma unroll
            for (int j = 0; j < 8; ++j) bl[j] = b1[j];
#pragma unroll
            for (int i = 0; i < 8; ++i) {
                const int r = rowg * 8 + i;
                const float2 p0 = unpk(hacc[i][0]), p1 = unpk(hacc[i][1]);
                const float2 p2 = unpk(hacc[i][2]), p3 = unpk(hacc[i][3]);
                float v[8] = {p0.x + bl[0], p0.y + bl[1], p1.x + bl[2], p1.y + bl[3],
                              p2.x + bl[4], p2.y + bl[5], p3.x + bl[6], p3.y + bl[7]};
#pragma unroll
                for (int j = 0; j < 8; ++j)
                    v[j] = 0.5f * v[j] * (1.f + erff(v[j] * 0.7071067811865476f));
                *reinterpret_cast<float4*>(sHF + r * PY + colg * 8)     = make_float4(v[0], v[1], v[2], v[3]);
                *reinterpret_cast<float4*>(sHF + r * PY + colg * 8 + 4) = make_float4(v[4], v[5], v[6], v[7]);
            }
        }
        // ---- FF2 partial: facc += hf_chunk @ f2w[:, ch*256..]^T ----
        const float* W2 = f2w + (size_t)m * 262144;  // rows=256 outcols, ld 1024
        for (int dt = 0; dt < 8; ++dt) {
            __syncthreads();
            ldA32<64>(sHF, PY, dt * 32, sAT, tid);
            ldW32(W2, 256, 1024, ch * 256 + dt * 32, sWT, tid);
            __syncthreads();
            mma8x8(sAT, sWT, facc, rowg, colg);
        }
    }

    // ---- epilogue: out = y + ff + f2b ----
    {
        float bl[8];
        const float* b2 = f2b + m * 256 + colg * 8;
#pragma unroll
        for (int j = 0; j < 8; ++j) bl[j] = b2[j];
#pragma unroll
        for (int i = 0; i < 8; ++i) {
            const int r = rowg * 8 + i;
            const float4 y0 = *reinterpret_cast<const float4*>(sY + r * PY + colg * 8);
            const float4 y1 = *reinterpret_cast<const float4*>(sY + r * PY + colg * 8 + 4);
            const float2 p0 = unpk(facc[i][0]), p1 = unpk(facc[i][1]);
            const float2 p2 = unpk(facc[i][2]), p3 = unpk(facc[i][3]);
            float4 o0 = make_float4(y0.x + p0.x + bl[0], y0.y + p0.y + bl[1],
                                    y0.z + p1.x + bl[2], y0.w + p1.y + bl[3]);
            float4 o1 = make_float4(y1.x + p2.x + bl[4], y1.y + p2.y + bl[5],
                                    y1.z + p3.x + bl[6], y1.w + p3.y + bl[7]);
            float* op = out + ((size_t)(b0 + r) * 4 + m) * 256 + colg * 8;
            *reinterpret_cast<float4*>(op)     = o0;
            *reinterpret_cast<float4*>(op + 4) = o1;
        }
    }
}

extern "C" void kernel_launch(void* const* d_in, const int* in_sizes, int n_in,
                              void* d_out, int out_size) {
    const float* x   = (const float*)d_in[0];
    const float* Wq  = (const float*)d_in[1];
    const float* bq  = (const float*)d_in[2];
    const float* Wk  = (const float*)d_in[3];
    const float* bk  = (const float*)d_in[4];
    const float* Wv  = (const float*)d_in[5];
    const float* bv  = (const float*)d_in[6];
    const float* Wo  = (const float*)d_in[7];
    const float* bo  = (const float*)d_in[8];
    const float* g1w = (const float*)d_in[9];
    const float* g1b = (const float*)d_in[10];
    const float* g2w = (const float*)d_in[11];
    const float* g2b = (const float*)d_in[12];
    const float* lng = (const float*)d_in[13];
    const float* lnb = (const float*)d_in[14];
    const float* f1w = (const float*)d_in[15];
    const float* f1b = (const float*)d_in[16];
    const float* f2w = (const float*)d_in[17];
    const float* f2b = (const float*)d_in[18];
    float* out = (float*)d_out;

    cudaFuncSetAttribute(gcma_part1, cudaFuncAttributeMaxDynamicSharedMemorySize, SM1_BYTES);
    cudaFuncSetAttribute(gcma_part2, cudaFuncAttributeMaxDynamicSharedMemorySize, SM2_BYTES);

    dim3 grid1(32768 / 16, 4, 1);
    gcma_part1<<<grid1, TPB, SM1_BYTES>>>(x, Wq, bq, Wk, bk, Wv, bv, Wo, bo,
                                          g1w, g1b, g2w, g2b, lng, lnb, out);
    dim3 grid2(32768 / 64, 4, 1);
    gcma_part2<<<grid2, TPB, SM2_BYTES>>>(f1w, f1b, f2w, f2b, out);
}